// round 12
// baseline (speedup 1.0000x reference)
#include <cuda_runtime.h>
#include <cuda_fp16.h>
#include <cstdint>

#define B_ 8
#define L_ 2048
#define D_ 1024
#define NTOT (B_ * L_)       /* 16384 rows */
#define K_ (2 * D_)          /* 2048 reduction dim */

#define BM 128               /* rows per CTA */
#define BN 128               /* cols: [0,64)=in-gate dims, [64,128)=fg-gate dims */
#define BK 32                /* fp16 k per stage */
#define PITCH 40             /* halves per row */
#define STAGES 4
#define KTILES (K_ / BK)     /* 64 */

#define A_HALVES (STAGES * BM * PITCH)           /* 20480 */
#define SMEM_HALVES (A_HALVES + STAGES * BN * PITCH)
#define SMEM_BYTES (SMEM_HALVES * 2)             /* 81920 -> 2 CTAs/SM */

/* fp16 scratch (device globals -- no allocation) */
__device__ __half h_X[NTOT * D_];     /* 32 MB */
__device__ __half h_AV[NTOT * D_];    /* 32 MB */
__device__ __half h_W[K_ * K_];       /* 8 MB  */
__device__ unsigned int g_flag[NTOT / BM];   /* per-bm "h_AV rows ready" */

__device__ __forceinline__ float sigmoidf_(float x) {
    return 1.0f / (1.0f + __expf(-x));
}

__device__ __forceinline__ void mma_f16(float* c, const uint32_t* a, const uint32_t* b) {
    asm volatile(
        "mma.sync.aligned.m16n8k16.row.col.f32.f16.f16.f32 "
        "{%0,%1,%2,%3}, {%4,%5,%6,%7}, {%8,%9}, {%0,%1,%2,%3};"
        : "+f"(c[0]), "+f"(c[1]), "+f"(c[2]), "+f"(c[3])
        : "r"(a[0]), "r"(a[1]), "r"(a[2]), "r"(a[3]), "r"(b[0]), "r"(b[1]));
}

__device__ __forceinline__ void ldsm_x4(uint32_t& r0, uint32_t& r1, uint32_t& r2,
                                        uint32_t& r3, uint32_t addr) {
    asm volatile("ldmatrix.sync.aligned.m8n8.x4.shared.b16 {%0,%1,%2,%3}, [%4];"
                 : "=r"(r0), "=r"(r1), "=r"(r2), "=r"(r3) : "r"(addr));
}

__device__ __forceinline__ void cp_async16(__half* s, const __half* g) {
    uint32_t sa = (uint32_t)__cvta_generic_to_shared(s);
    asm volatile("cp.async.cg.shared.global [%0], [%1], 16;" :: "r"(sa), "l"(g));
}
__device__ __forceinline__ void cp_commit() {
    asm volatile("cp.async.commit_group;");
}
template <int N>
__device__ __forceinline__ void cp_wait() {
    asm volatile("cp.async.wait_group %0;" :: "n"(N));
}

__device__ __forceinline__ uint2 pack_h4(float a, float b, float c, float d) {
    __half2 lo = __floats2half2_rn(a, b);
    __half2 hi = __floats2half2_rn(c, d);
    uint2 u;
    u.x = *reinterpret_cast<uint32_t*>(&lo);
    u.y = *reinterpret_cast<uint32_t*>(&hi);
    return u;
}

/* ======================= cumulative average helpers ======================= */
#define CHUNK 16
#define NCH (L_ / CHUNK)   /* 128 */
#define D4 (D_ / 4)        /* 256 */
#define PART_BLOCKS (B_ * NCH)   /* 1024 */
#define CVT_BLOCKS 256
__device__ float g_part[B_ * NCH * D_];   /* 4 MB */

/* Pass 1: chunk sums + fused X->fp16; extra blocks convert W; zero flags. */
__global__ void cumavg_part_cvt(const float* __restrict__ x,
                                const float* __restrict__ w) {
    int bid = blockIdx.x;
    if (bid >= PART_BLOCKS) {
        if (bid == PART_BLOCKS && threadIdx.x < NTOT / BM)
            g_flag[threadIdx.x] = 0u;
        int i0 = (bid - PART_BLOCKS) * 256 + threadIdx.x;
        const float4* src = reinterpret_cast<const float4*>(w);
        uint2* dst = reinterpret_cast<uint2*>(h_W);
#pragma unroll
        for (int j = 0; j < (K_ * K_ / 4) / (CVT_BLOCKS * 256); ++j) {
            int i = i0 + j * CVT_BLOCKS * 256;
            float4 v = src[i];
            dst[i] = pack_h4(v.x, v.y, v.z, v.w);
        }
        return;
    }
    int b = bid >> 7, c = bid & 127;
    int d4 = threadIdx.x;
    size_t base = ((size_t)b * L_ + c * CHUNK) * D4 + d4;
    const float4* px = reinterpret_cast<const float4*>(x) + base;
    uint2* ph = reinterpret_cast<uint2*>(h_X) + base;
    float4 s = {0.f, 0.f, 0.f, 0.f};
#pragma unroll
    for (int t = 0; t < CHUNK; ++t) {
        float4 v = px[(size_t)t * D4];
        s.x += v.x; s.y += v.y; s.z += v.z; s.w += v.w;
        ph[(size_t)t * D4] = pack_h4(v.x, v.y, v.z, v.w);
    }
    reinterpret_cast<float4*>(g_part)[(b * NCH + c) * D4 + d4] = s;
}

/* Pass 2: exclusive prefix over the NCH chunk sums. 8 blocks x 256 thr. */
__global__ void chunk_prefix() {
    int b = blockIdx.x, d4 = threadIdx.x;
    float4* gp = reinterpret_cast<float4*>(g_part);
    float4 run = {0.f, 0.f, 0.f, 0.f};
#pragma unroll 8
    for (int c = 0; c < NCH; ++c) {
        size_t i = (size_t)(b * NCH + c) * D4 + d4;
        float4 v = gp[i];
        gp[i] = run;
        run.x += v.x; run.y += v.y; run.z += v.z; run.w += v.w;
    }
}

/* ======================= fp16 tensor GEMM + fused gating ================ */
/* 4 warps, warp grid 2(m) x 2(n), warp tile 64x64, f32 accumulators.
   bn==0 CTAs run the cumavg scan for their own 128 rows as a prologue
   (writes avg f32 + h_AV f16, releases g_flag[bm]); all CTAs of that bm
   spin on the flag at kt==29, just before the first h_AV prefetch (kt+3=32).
   Single __syncthreads per ktile (CUTLASS multistage pattern). */
__global__ __launch_bounds__(128, 2)
void gate_gemm_f16(const float* __restrict__ X,
                   float* __restrict__ avg,
                   const float* __restrict__ bias,
                   float* __restrict__ out)
{
    extern __shared__ __half smem[];
    __half* Asm = smem;                  /* [STAGES][BM][PITCH] */
    __half* Bsm = smem + A_HALVES;       /* [STAGES][BN][PITCH] */

    const int tid    = threadIdx.x;
    const int lane   = tid & 31;
    const int wid    = tid >> 5;         /* 0..3 */
    const int warp_m = wid & 1;          /* 2 warps along M (64 rows each) */
    const int warp_n = wid >> 1;         /* 2 warps along N (32 dims each) */
    const int lr     = lane >> 2;
    const int lc     = lane & 3;

    const int bn   = blockIdx.x;         /* 0..15 -> dims [bn*64, bn*64+64) */
    const int bm   = blockIdx.y;         /* 0..127 */
    const int row0 = bm * BM;
    const int d0   = bn * 64;

    /* -------- prologue: bn==0 produces h_AV/avg rows [row0, row0+128) ---- */
    if (bn == 0) {
        const int b  = row0 >> 11;            /* / L_ */
        const int c0 = (row0 & (L_ - 1)) >> 4; /* starting chunk, 8 chunks */
        const float4* px4 = reinterpret_cast<const float4*>(X);
        const float4* gp4 = reinterpret_cast<const float4*>(g_part);
        float4* pa4 = reinterpret_cast<float4*>(avg);
        uint2*  ph2 = reinterpret_cast<uint2*>(h_AV);
#pragma unroll
        for (int half = 0; half < 2; ++half) {
            int d4 = tid + half * 128;
#pragma unroll
            for (int c = c0; c < c0 + 8; ++c) {
                float4 run = gp4[(size_t)(b * NCH + c) * D4 + d4];
                int t0g = c * CHUNK;
                size_t base = ((size_t)b * L_ + t0g) * D4 + d4;
#pragma unroll
                for (int t = 0; t < CHUNK; ++t) {
                    float4 v = px4[base + (size_t)t * D4];
                    run.x += v.x; run.y += v.y; run.z += v.z; run.w += v.w;
                    float r = 1.0f / (float)(t0g + t + 1);
                    float4 a = {run.x * r, run.y * r, run.z * r, run.w * r};
                    pa4[base + (size_t)t * D4] = a;
                    ph2[base + (size_t)t * D4] = pack_h4(a.x, a.y, a.z, a.w);
                }
            }
        }
        __threadfence();
        __syncthreads();
        if (tid == 0) atomicExch(&g_flag[bm], 1u);
    }

    const uint32_t As_u32 = (uint32_t)__cvta_generic_to_shared(Asm);
    const uint32_t Bs_u32 = (uint32_t)__cvta_generic_to_shared(Bsm);

    const int a_lane = (lane & 15) * PITCH + (lane >> 4) * 8;
    const int b_lane = ((lane & 7) + ((lane >> 4) << 3)) * PITCH + (((lane >> 3) & 1) << 3);

    float acc[4][8][4];
#pragma unroll
    for (int i = 0; i < 4; i++)
#pragma unroll
        for (int j = 0; j < 8; j++)
#pragma unroll
            for (int r = 0; r < 4; r++) acc[i][j][r] = 0.0f;

    /* 128 threads: A = 512 chunks (4/thread), B = 512 chunks (4/thread) */
    auto load_tiles = [&](int kt, int stg) {
        const int kb = kt * BK;
        const __half* asrc = (kb < D_) ? h_X : h_AV;
        const int akb = (kb < D_) ? kb : (kb - D_);
        __half* As = Asm + stg * (BM * PITCH);
        __half* Bs = Bsm + stg * (BN * PITCH);
#pragma unroll
        for (int j = 0; j < 4; ++j) {
            int idx = tid + 128 * j;
            int row = idx >> 2;
            int off = (idx & 3) * 8;
            cp_async16(As + row * PITCH + off,
                       asrc + (size_t)(row0 + row) * D_ + akb + off);
        }
#pragma unroll
        for (int j = 0; j < 4; ++j) {
            int idx = tid + 128 * j;
            int n   = idx >> 2;
            int off = (idx & 3) * 8;
            int o = (n < 64) ? (d0 + n) : (D_ + d0 + (n - 64));
            cp_async16(Bs + n * PITCH + off,
                       h_W + (size_t)o * K_ + kb + off);
        }
        cp_commit();
    };

    load_tiles(0, 0);
    load_tiles(1, 1);
    load_tiles(2, 2);

    for (int kt = 0; kt < KTILES; ++kt) {
        if (kt + 3 < KTILES) cp_wait<2>();
        else                 cp_wait<0>();
        __syncthreads();

        /* first h_AV prefetch is load_tiles(32) at kt==29: gate on the flag */
        if (kt == 29) {
            if (tid == 0) {
                uint32_t f;
                do {
                    asm volatile("ld.acquire.gpu.global.u32 %0, [%1];"
                                 : "=r"(f) : "l"(g_flag + bm) : "memory");
                    if (!f) __nanosleep(64);
                } while (!f);
            }
            __syncthreads();
        }

        if (kt + 3 < KTILES) load_tiles(kt + 3, (kt + 3) & 3);

        const int st = kt & 3;
        const uint32_t a_base = As_u32 + 2 * (st * (BM * PITCH) + warp_m * 64 * PITCH + a_lane);
        const uint32_t b_base = Bs_u32 + 2 * (st * (BN * PITCH) + b_lane);

#pragma unroll
        for (int ks = 0; ks < 2; ++ks) {
            uint32_t aR[4][4];
            uint32_t bR[8][2];
#pragma unroll
            for (int mt = 0; mt < 4; ++mt)
                ldsm_x4(aR[mt][0], aR[mt][1], aR[mt][2], aR[mt][3],
                        a_base + 2 * (mt * 16 * PITCH + ks * 16));
#pragma unroll
            for (int ntp = 0; ntp < 4; ++ntp) {
                int nt = 2 * ntp;
                int fnt = (nt < 4) ? (warp_n * 32 + nt * 8)
                                   : (64 + warp_n * 32 + (nt - 4) * 8);
                ldsm_x4(bR[nt][0], bR[nt][1], bR[nt + 1][0], bR[nt + 1][1],
                        b_base + 2 * (fnt * PITCH + ks * 16));
            }
#pragma unroll
            for (int mt = 0; mt < 4; ++mt)
#pragma unroll
                for (int nt = 0; nt < 8; ++nt)
                    mma_f16(acc[mt][nt], aR[mt], bR[nt]);
        }
    }

    /* ---- fused epilogue: thread holds contiguous d pair (2lc, 2lc+1) ---- */
#pragma unroll
    for (int mt = 0; mt < 4; ++mt) {
#pragma unroll
        for (int nt = 0; nt < 4; ++nt) {
            int d = d0 + warp_n * 32 + nt * 8 + 2 * lc;
            float2 bin = *reinterpret_cast<const float2*>(bias + d);
            float2 bfg = *reinterpret_cast<const float2*>(bias + D_ + d);

            int row = row0 + warp_m * 64 + mt * 16 + lr;
            {
                size_t off = (size_t)row * D_ + d;
                float2 xv = *reinterpret_cast<const float2*>(X + off);
                float2 av = *reinterpret_cast<const float2*>(avg + off);
                float2 o;
                o.x = sigmoidf_(acc[mt][nt][0] + bin.x) * xv.x +
                      sigmoidf_(acc[mt][nt + 4][0] + bfg.x) * av.x;
                o.y = sigmoidf_(acc[mt][nt][1] + bin.y) * xv.y +
                      sigmoidf_(acc[mt][nt + 4][1] + bfg.y) * av.y;
                *reinterpret_cast<float2*>(out + off) = o;
            }
            {
                size_t off = (size_t)(row + 8) * D_ + d;
                float2 xv = *reinterpret_cast<const float2*>(X + off);
                float2 av = *reinterpret_cast<const float2*>(avg + off);
                float2 o;
                o.x = sigmoidf_(acc[mt][nt][2] + bin.x) * xv.x +
                      sigmoidf_(acc[mt][nt + 4][2] + bfg.x) * av.x;
                o.y = sigmoidf_(acc[mt][nt][3] + bin.y) * xv.y +
                      sigmoidf_(acc[mt][nt + 4][3] + bfg.y) * av.y;
                *reinterpret_cast<float2*>(out + off) = o;
            }
        }
    }
}

/* ======================= host ======================= */
extern "C" void kernel_launch(void* const* d_in, const int* in_sizes, int n_in,
                              void* d_out, int out_size) {
    (void)in_sizes; (void)n_in; (void)out_size;
    const float* X    = (const float*)d_in[0];
    const float* W    = (const float*)d_in[1];
    const float* bias = (const float*)d_in[2];

    float* gating = (float*)d_out;
    float* avg    = (float*)d_out + (size_t)NTOT * D_;

    static bool attr_set = false;
    if (!attr_set) {
        cudaFuncSetAttribute(gate_gemm_f16,
                             cudaFuncAttributeMaxDynamicSharedMemorySize, SMEM_BYTES);
        attr_set = true;
    }

    cumavg_part_cvt<<<PART_BLOCKS + CVT_BLOCKS, 256>>>(X, W);
    chunk_prefix<<<B_, 256>>>();

    dim3 grid(D_ / 64, NTOT / BM);   /* (16, 128) */
    gate_gemm_f16<<<grid, 128, SMEM_BYTES>>>(X, avg, bias, gating);
}

// round 13
// speedup vs baseline: 1.5299x; 1.5299x over previous
#include <cuda_runtime.h>
#include <cuda_fp16.h>
#include <cstdint>

#define B_ 8
#define L_ 2048
#define D_ 1024
#define NTOT (B_ * L_)       /* 16384 rows */
#define K_ (2 * D_)          /* 2048 reduction dim */

#define BM 128               /* rows per CTA */
#define BN 128               /* cols: [0,64)=in-gate dims, [64,128)=fg-gate dims */
#define BK 32                /* fp16 k per stage */
#define PITCH 40             /* halves per row */
#define STAGES 4
#define KTILES (K_ / BK)     /* 64 */

#define A_HALVES (STAGES * BM * PITCH)           /* 20480 */
#define SMEM_HALVES (A_HALVES + STAGES * BN * PITCH)
#define SMEM_BYTES (SMEM_HALVES * 2)             /* 81920 -> 2 CTAs/SM */

/* fp16 scratch (device globals -- no allocation) */
__device__ __half h_X[NTOT * D_];     /* 32 MB */
__device__ __half h_AV[NTOT * D_];    /* 32 MB */
__device__ __half h_W[K_ * K_];       /* 8 MB  */
__device__ unsigned int scan_cnt[NTOT / BM];   /* per-bm scan arrivals (0..16) */

__device__ __forceinline__ float sigmoidf_(float x) {
    return 1.0f / (1.0f + __expf(-x));
}

__device__ __forceinline__ void mma_f16(float* c, const uint32_t* a, const uint32_t* b) {
    asm volatile(
        "mma.sync.aligned.m16n8k16.row.col.f32.f16.f16.f32 "
        "{%0,%1,%2,%3}, {%4,%5,%6,%7}, {%8,%9}, {%0,%1,%2,%3};"
        : "+f"(c[0]), "+f"(c[1]), "+f"(c[2]), "+f"(c[3])
        : "r"(a[0]), "r"(a[1]), "r"(a[2]), "r"(a[3]), "r"(b[0]), "r"(b[1]));
}

__device__ __forceinline__ void ldsm_x4(uint32_t& r0, uint32_t& r1, uint32_t& r2,
                                        uint32_t& r3, uint32_t addr) {
    asm volatile("ldmatrix.sync.aligned.m8n8.x4.shared.b16 {%0,%1,%2,%3}, [%4];"
                 : "=r"(r0), "=r"(r1), "=r"(r2), "=r"(r3) : "r"(addr));
}

__device__ __forceinline__ void cp_async16(__half* s, const __half* g) {
    uint32_t sa = (uint32_t)__cvta_generic_to_shared(s);
    asm volatile("cp.async.cg.shared.global [%0], [%1], 16;" :: "r"(sa), "l"(g));
}
__device__ __forceinline__ void cp_commit() {
    asm volatile("cp.async.commit_group;");
}
template <int N>
__device__ __forceinline__ void cp_wait() {
    asm volatile("cp.async.wait_group %0;" :: "n"(N));
}

__device__ __forceinline__ uint2 pack_h4(float a, float b, float c, float d) {
    __half2 lo = __floats2half2_rn(a, b);
    __half2 hi = __floats2half2_rn(c, d);
    uint2 u;
    u.x = *reinterpret_cast<uint32_t*>(&lo);
    u.y = *reinterpret_cast<uint32_t*>(&hi);
    return u;
}

/* ======================= cumulative average helpers ======================= */
#define CHUNK 16
#define NCH (L_ / CHUNK)   /* 128 */
#define D4 (D_ / 4)        /* 256 */
#define PART_BLOCKS (B_ * NCH)   /* 1024 */
#define CVT_BLOCKS 256
__device__ float g_part[B_ * NCH * D_];   /* 4 MB */

/* Pass 1: chunk sums + fused X->fp16; extra blocks convert W; zero counters. */
__global__ void cumavg_part_cvt(const float* __restrict__ x,
                                const float* __restrict__ w) {
    int bid = blockIdx.x;
    if (bid >= PART_BLOCKS) {
        if (bid == PART_BLOCKS && threadIdx.x < NTOT / BM)
            scan_cnt[threadIdx.x] = 0u;
        int i0 = (bid - PART_BLOCKS) * 256 + threadIdx.x;
        const float4* src = reinterpret_cast<const float4*>(w);
        uint2* dst = reinterpret_cast<uint2*>(h_W);
#pragma unroll
        for (int j = 0; j < (K_ * K_ / 4) / (CVT_BLOCKS * 256); ++j) {
            int i = i0 + j * CVT_BLOCKS * 256;
            float4 v = src[i];
            dst[i] = pack_h4(v.x, v.y, v.z, v.w);
        }
        return;
    }
    int b = bid >> 7, c = bid & 127;
    int d4 = threadIdx.x;
    size_t base = ((size_t)b * L_ + c * CHUNK) * D4 + d4;
    const float4* px = reinterpret_cast<const float4*>(x) + base;
    uint2* ph = reinterpret_cast<uint2*>(h_X) + base;
    float4 s = {0.f, 0.f, 0.f, 0.f};
#pragma unroll
    for (int t = 0; t < CHUNK; ++t) {
        float4 v = px[(size_t)t * D4];
        s.x += v.x; s.y += v.y; s.z += v.z; s.w += v.w;
        ph[(size_t)t * D4] = pack_h4(v.x, v.y, v.z, v.w);
    }
    reinterpret_cast<float4*>(g_part)[(b * NCH + c) * D4 + d4] = s;
}

/* Pass 2: exclusive prefix over the NCH chunk sums. 8 blocks x 256 thr. */
__global__ void chunk_prefix() {
    int b = blockIdx.x, d4 = threadIdx.x;
    float4* gp = reinterpret_cast<float4*>(g_part);
    float4 run = {0.f, 0.f, 0.f, 0.f};
#pragma unroll 8
    for (int c = 0; c < NCH; ++c) {
        size_t i = (size_t)(b * NCH + c) * D4 + d4;
        float4 v = gp[i];
        gp[i] = run;
        run.x += v.x; run.y += v.y; run.z += v.z; run.w += v.w;
    }
}

/* ======================= fp16 tensor GEMM + fused gating ================ */
/* 4 warps, warp tile 64x64, f32 acc, single bar per ktile (R11 mainloop).
   Prologue: each of the 16 CTAs sharing a bm scans 1/16 of that bm's
   cumavg rows (one float4 column per thread; prefix guaranteed done by
   kernel ordering), then arrives on scan_cnt[bm]. Mainloop gates at
   kt==29 (just before the first h_AV prefetch, kt+3==32) on cnt==16.
   While a CTA's prologue waits on DRAM, the co-resident CTA keeps the
   HMMA pipe full (R9: 1 warp/SMSP saturates it). */
__global__ __launch_bounds__(128, 2)
void gate_gemm_f16(const float* __restrict__ X,
                   float* __restrict__ avg,
                   const float* __restrict__ bias,
                   float* __restrict__ out)
{
    extern __shared__ __half smem[];
    __half* Asm = smem;                  /* [STAGES][BM][PITCH] */
    __half* Bsm = smem + A_HALVES;       /* [STAGES][BN][PITCH] */

    const int tid    = threadIdx.x;
    const int lane   = tid & 31;
    const int wid    = tid >> 5;         /* 0..3 */
    const int warp_m = wid & 1;          /* 2 warps along M (64 rows each) */
    const int warp_n = wid >> 1;         /* 2 warps along N (32 dims each) */
    const int lr     = lane >> 2;
    const int lc     = lane & 3;

    const int bn   = blockIdx.x;         /* 0..15 -> dims [bn*64, bn*64+64) */
    const int bm   = blockIdx.y;         /* 0..127 */
    const int row0 = bm * BM;
    const int d0   = bn * 64;

    /* -------- prologue: this CTA's 1/16 share of bm's cumavg scan ------- */
    {
        const int b  = bm >> 4;                 /* batch index */
        const int c0 = (bm & 15) * 8;           /* first of 8 chunks */
        const int cc = c0 + (bn >> 1);          /* this CTA's chunk */
        const int d4 = ((bn & 1) << 7) + tid;   /* this thread's column */
        const int t0g = cc * CHUNK;

        float4 run = reinterpret_cast<const float4*>(g_part)[(b * NCH + cc) * D4 + d4];
        size_t base = ((size_t)b * L_ + t0g) * D4 + d4;
        const float4* px4 = reinterpret_cast<const float4*>(X);
        float4* pa4 = reinterpret_cast<float4*>(avg);
        uint2*  ph2 = reinterpret_cast<uint2*>(h_AV);
#pragma unroll
        for (int t = 0; t < CHUNK; ++t) {
            float4 v = px4[base + (size_t)t * D4];
            run.x += v.x; run.y += v.y; run.z += v.z; run.w += v.w;
            float r = 1.0f / (float)(t0g + t + 1);
            float4 a = {run.x * r, run.y * r, run.z * r, run.w * r};
            pa4[base + (size_t)t * D4] = a;
            ph2[base + (size_t)t * D4] = pack_h4(a.x, a.y, a.z, a.w);
        }
        __threadfence();
        __syncthreads();
        if (tid == 0) atomicAdd(&scan_cnt[bm], 1u);
    }

    const uint32_t As_u32 = (uint32_t)__cvta_generic_to_shared(Asm);
    const uint32_t Bs_u32 = (uint32_t)__cvta_generic_to_shared(Bsm);

    const int a_lane = (lane & 15) * PITCH + (lane >> 4) * 8;
    const int b_lane = ((lane & 7) + ((lane >> 4) << 3)) * PITCH + (((lane >> 3) & 1) << 3);

    float acc[4][8][4];
#pragma unroll
    for (int i = 0; i < 4; i++)
#pragma unroll
        for (int j = 0; j < 8; j++)
#pragma unroll
            for (int r = 0; r < 4; r++) acc[i][j][r] = 0.0f;

    /* 128 threads: A = 512 chunks (4/thread), B = 512 chunks (4/thread) */
    auto load_tiles = [&](int kt, int stg) {
        const int kb = kt * BK;
        const __half* asrc = (kb < D_) ? h_X : h_AV;
        const int akb = (kb < D_) ? kb : (kb - D_);
        __half* As = Asm + stg * (BM * PITCH);
        __half* Bs = Bsm + stg * (BN * PITCH);
#pragma unroll
        for (int j = 0; j < 4; ++j) {
            int idx = tid + 128 * j;
            int row = idx >> 2;
            int off = (idx & 3) * 8;
            cp_async16(As + row * PITCH + off,
                       asrc + (size_t)(row0 + row) * D_ + akb + off);
        }
#pragma unroll
        for (int j = 0; j < 4; ++j) {
            int idx = tid + 128 * j;
            int n   = idx >> 2;
            int off = (idx & 3) * 8;
            int o = (n < 64) ? (d0 + n) : (D_ + d0 + (n - 64));
            cp_async16(Bs + n * PITCH + off,
                       h_W + (size_t)o * K_ + kb + off);
        }
        cp_commit();
    };

    load_tiles(0, 0);
    load_tiles(1, 1);
    load_tiles(2, 2);

    for (int kt = 0; kt < KTILES; ++kt) {
        if (kt + 3 < KTILES) cp_wait<2>();
        else                 cp_wait<0>();
        __syncthreads();

        /* first h_AV prefetch is load_tiles(32) at kt==29: gate on group */
        if (kt == 29) {
            if (tid == 0) {
                uint32_t f;
                do {
                    asm volatile("ld.acquire.gpu.global.u32 %0, [%1];"
                                 : "=r"(f) : "l"(scan_cnt + bm) : "memory");
                    if (f < 16u) __nanosleep(64);
                } while (f < 16u);
            }
            __syncthreads();
        }

        if (kt + 3 < KTILES) load_tiles(kt + 3, (kt + 3) & 3);

        const int st = kt & 3;
        const uint32_t a_base = As_u32 + 2 * (st * (BM * PITCH) + warp_m * 64 * PITCH + a_lane);
        const uint32_t b_base = Bs_u32 + 2 * (st * (BN * PITCH) + b_lane);

#pragma unroll
        for (int ks = 0; ks < 2; ++ks) {
            uint32_t aR[4][4];
            uint32_t bR[8][2];
#pragma unroll
            for (int mt = 0; mt < 4; ++mt)
                ldsm_x4(aR[mt][0], aR[mt][1], aR[mt][2], aR[mt][3],
                        a_base + 2 * (mt * 16 * PITCH + ks * 16));
#pragma unroll
            for (int ntp = 0; ntp < 4; ++ntp) {
                int nt = 2 * ntp;
                int fnt = (nt < 4) ? (warp_n * 32 + nt * 8)
                                   : (64 + warp_n * 32 + (nt - 4) * 8);
                ldsm_x4(bR[nt][0], bR[nt][1], bR[nt + 1][0], bR[nt + 1][1],
                        b_base + 2 * (fnt * PITCH + ks * 16));
            }
#pragma unroll
            for (int mt = 0; mt < 4; ++mt)
#pragma unroll
                for (int nt = 0; nt < 8; ++nt)
                    mma_f16(acc[mt][nt], aR[mt], bR[nt]);
        }
    }

    /* ---- fused epilogue: thread holds contiguous d pair (2lc, 2lc+1) ---- */
#pragma unroll
    for (int mt = 0; mt < 4; ++mt) {
#pragma unroll
        for (int nt = 0; nt < 4; ++nt) {
            int d = d0 + warp_n * 32 + nt * 8 + 2 * lc;
            float2 bin = *reinterpret_cast<const float2*>(bias + d);
            float2 bfg = *reinterpret_cast<const float2*>(bias + D_ + d);

            int row = row0 + warp_m * 64 + mt * 16 + lr;
            {
                size_t off = (size_t)row * D_ + d;
                float2 xv = *reinterpret_cast<const float2*>(X + off);
                float2 av = *reinterpret_cast<const float2*>(avg + off);
                float2 o;
                o.x = sigmoidf_(acc[mt][nt][0] + bin.x) * xv.x +
                      sigmoidf_(acc[mt][nt + 4][0] + bfg.x) * av.x;
                o.y = sigmoidf_(acc[mt][nt][1] + bin.y) * xv.y +
                      sigmoidf_(acc[mt][nt + 4][1] + bfg.y) * av.y;
                *reinterpret_cast<float2*>(out + off) = o;
            }
            {
                size_t off = (size_t)(row + 8) * D_ + d;
                float2 xv = *reinterpret_cast<const float2*>(X + off);
                float2 av = *reinterpret_cast<const float2*>(avg + off);
                float2 o;
                o.x = sigmoidf_(acc[mt][nt][2] + bin.x) * xv.x +
                      sigmoidf_(acc[mt][nt + 4][2] + bfg.x) * av.x;
                o.y = sigmoidf_(acc[mt][nt][3] + bin.y) * xv.y +
                      sigmoidf_(acc[mt][nt + 4][3] + bfg.y) * av.y;
                *reinterpret_cast<float2*>(out + off) = o;
            }
        }
    }
}

/* ======================= host ======================= */
extern "C" void kernel_launch(void* const* d_in, const int* in_sizes, int n_in,
                              void* d_out, int out_size) {
    (void)in_sizes; (void)n_in; (void)out_size;
    const float* X    = (const float*)d_in[0];
    const float* W    = (const float*)d_in[1];
    const float* bias = (const float*)d_in[2];

    float* gating = (float*)d_out;
    float* avg    = (float*)d_out + (size_t)NTOT * D_;

    static bool attr_set = false;
    if (!attr_set) {
        cudaFuncSetAttribute(gate_gemm_f16,
                             cudaFuncAttributeMaxDynamicSharedMemorySize, SMEM_BYTES);
        attr_set = true;
    }

    cumavg_part_cvt<<<PART_BLOCKS + CVT_BLOCKS, 256>>>(X, W);
    chunk_prefix<<<B_, 256>>>();

    dim3 grid(D_ / 64, NTOT / BM);   /* (16, 128) */
    gate_gemm_f16<<<grid, 128, SMEM_BYTES>>>(X, avg, bias, gating);
}

// round 14
// speedup vs baseline: 1.6706x; 1.0920x over previous
#include <cuda_runtime.h>
#include <cuda_fp16.h>
#include <cstdint>

#define B_ 8
#define L_ 2048
#define D_ 1024
#define NTOT (B_ * L_)       /* 16384 rows */
#define K_ (2 * D_)          /* 2048 reduction dim */

#define BM 128               /* rows per CTA */
#define BN 128               /* cols: [0,64)=in-gate dims, [64,128)=fg-gate dims */
#define BK 64                /* fp16 k per stage */
#define PITCH 72             /* halves per row: 144B, 16B-aligned, conflict-free */
#define STAGES 3
#define KTILES (K_ / BK)     /* 32 */

#define A_HALVES (STAGES * BM * PITCH)           /* 27648 */
#define SMEM_HALVES (A_HALVES + STAGES * BN * PITCH)
#define SMEM_BYTES (SMEM_HALVES * 2)             /* 110592 -> 2 CTAs/SM */

/* fp16 scratch (device globals -- no allocation) */
__device__ __half h_X[NTOT * D_];     /* 32 MB */
__device__ __half h_AV[NTOT * D_];    /* 32 MB */
__device__ __half h_W[K_ * K_];       /* 8 MB  */

__device__ __forceinline__ float sigmoidf_(float x) {
    return 1.0f / (1.0f + __expf(-x));
}

__device__ __forceinline__ void mma_f16(float* c, const uint32_t* a, const uint32_t* b) {
    asm volatile(
        "mma.sync.aligned.m16n8k16.row.col.f32.f16.f16.f32 "
        "{%0,%1,%2,%3}, {%4,%5,%6,%7}, {%8,%9}, {%0,%1,%2,%3};"
        : "+f"(c[0]), "+f"(c[1]), "+f"(c[2]), "+f"(c[3])
        : "r"(a[0]), "r"(a[1]), "r"(a[2]), "r"(a[3]), "r"(b[0]), "r"(b[1]));
}

__device__ __forceinline__ void ldsm_x4(uint32_t& r0, uint32_t& r1, uint32_t& r2,
                                        uint32_t& r3, uint32_t addr) {
    asm volatile("ldmatrix.sync.aligned.m8n8.x4.shared.b16 {%0,%1,%2,%3}, [%4];"
                 : "=r"(r0), "=r"(r1), "=r"(r2), "=r"(r3) : "r"(addr));
}

__device__ __forceinline__ void cp_async16(__half* s, const __half* g) {
    uint32_t sa = (uint32_t)__cvta_generic_to_shared(s);
    asm volatile("cp.async.cg.shared.global [%0], [%1], 16;" :: "r"(sa), "l"(g));
}
__device__ __forceinline__ void cp_commit() {
    asm volatile("cp.async.commit_group;");
}
template <int N>
__device__ __forceinline__ void cp_wait() {
    asm volatile("cp.async.wait_group %0;" :: "n"(N));
}

__device__ __forceinline__ uint2 pack_h4(float a, float b, float c, float d) {
    __half2 lo = __floats2half2_rn(a, b);
    __half2 hi = __floats2half2_rn(c, d);
    uint2 u;
    u.x = *reinterpret_cast<uint32_t*>(&lo);
    u.y = *reinterpret_cast<uint32_t*>(&hi);
    return u;
}

/* ======================= cumulative average (3-pass, float4) =========== */
#define CHUNK 16
#define NCH (L_ / CHUNK)   /* 128 */
#define D4 (D_ / 4)        /* 256 */
#define PART_BLOCKS (B_ * NCH)   /* 1024 */
#define CVT_BLOCKS 256
__device__ float g_part[B_ * NCH * D_];   /* 4 MB */

__global__ void cumavg_part_cvt(const float* __restrict__ x,
                                const float* __restrict__ w) {
    int bid = blockIdx.x;
    if (bid >= PART_BLOCKS) {
        int i0 = (bid - PART_BLOCKS) * 256 + threadIdx.x;
        const float4* src = reinterpret_cast<const float4*>(w);
        uint2* dst = reinterpret_cast<uint2*>(h_W);
#pragma unroll
        for (int j = 0; j < (K_ * K_ / 4) / (CVT_BLOCKS * 256); ++j) {
            int i = i0 + j * CVT_BLOCKS * 256;
            float4 v = src[i];
            dst[i] = pack_h4(v.x, v.y, v.z, v.w);
        }
        return;
    }
    int b = bid >> 7, c = bid & 127;
    int d4 = threadIdx.x;
    size_t base = ((size_t)b * L_ + c * CHUNK) * D4 + d4;
    const float4* px = reinterpret_cast<const float4*>(x) + base;
    uint2* ph = reinterpret_cast<uint2*>(h_X) + base;
    float4 s = {0.f, 0.f, 0.f, 0.f};
#pragma unroll
    for (int t = 0; t < CHUNK; ++t) {
        float4 v = px[(size_t)t * D4];
        s.x += v.x; s.y += v.y; s.z += v.z; s.w += v.w;
        ph[(size_t)t * D4] = pack_h4(v.x, v.y, v.z, v.w);
    }
    reinterpret_cast<float4*>(g_part)[(b * NCH + c) * D4 + d4] = s;
}

__global__ void chunk_prefix() {
    int b = blockIdx.x, d4 = threadIdx.x;
    float4* gp = reinterpret_cast<float4*>(g_part);
    float4 run = {0.f, 0.f, 0.f, 0.f};
#pragma unroll 8
    for (int c = 0; c < NCH; ++c) {
        size_t i = (size_t)(b * NCH + c) * D4 + d4;
        float4 v = gp[i];
        gp[i] = run;
        run.x += v.x; run.y += v.y; run.z += v.z; run.w += v.w;
    }
}

__global__ void cumavg_scan_v3(const float* __restrict__ x, float* __restrict__ avg) {
    int b = blockIdx.x >> 7, c = blockIdx.x & 127;
    int d4 = threadIdx.x;
    int t0 = c * CHUNK;
    float4 run = reinterpret_cast<const float4*>(g_part)[(b * NCH + c) * D4 + d4];
    size_t base = ((size_t)b * L_ + t0) * D4 + d4;
    const float4* px = reinterpret_cast<const float4*>(x) + base;
    float4* pa = reinterpret_cast<float4*>(avg) + base;
    uint2* ph = reinterpret_cast<uint2*>(h_AV) + base;
#pragma unroll
    for (int t = 0; t < CHUNK; ++t) {
        float4 v = px[(size_t)t * D4];
        run.x += v.x; run.y += v.y; run.z += v.z; run.w += v.w;
        float r = 1.0f / (float)(t0 + t + 1);
        float4 a = {run.x * r, run.y * r, run.z * r, run.w * r};
        pa[(size_t)t * D4] = a;
        ph[(size_t)t * D4] = pack_h4(a.x, a.y, a.z, a.w);
    }
}

/* ======================= fp16 tensor GEMM + fused gating ================ */
/* 4 warps, warp grid 2(m) x 2(n), warp tile 64x64, f32 accumulators.
   BK=64, STAGES=3, single bar per ktile: 32 barriers total (was 64).
   wait group kt -> bar -> issue load(kt+2) into slot (kt+2)%3 == (kt-1)%3
   (safe: bar guarantees all warps finished MMA(kt-1)) -> MMA(kt). */
__global__ __launch_bounds__(128, 2)
void gate_gemm_f16(const float* __restrict__ X,
                   const float* __restrict__ AV,
                   const float* __restrict__ bias,
                   float* __restrict__ out)
{
    extern __shared__ __half smem[];
    __half* Asm = smem;                  /* [STAGES][BM][PITCH] */
    __half* Bsm = smem + A_HALVES;       /* [STAGES][BN][PITCH] */

    const int tid    = threadIdx.x;
    const int lane   = tid & 31;
    const int wid    = tid >> 5;         /* 0..3 */
    const int warp_m = wid & 1;          /* 2 warps along M (64 rows each) */
    const int warp_n = wid >> 1;         /* 2 warps along N (32 dims each) */
    const int lr     = lane >> 2;
    const int lc     = lane & 3;

    const int bn   = blockIdx.x;         /* 0..15 -> dims [bn*64, bn*64+64) */
    const int bm   = blockIdx.y;         /* 0..127 */
    const int row0 = bm * BM;
    const int d0   = bn * 64;

    const uint32_t As_u32 = (uint32_t)__cvta_generic_to_shared(Asm);
    const uint32_t Bs_u32 = (uint32_t)__cvta_generic_to_shared(Bsm);

    const int a_lane = (lane & 15) * PITCH + (lane >> 4) * 8;
    const int b_lane = ((lane & 7) + ((lane >> 4) << 3)) * PITCH + (((lane >> 3) & 1) << 3);

    float acc[4][8][4];
#pragma unroll
    for (int i = 0; i < 4; i++)
#pragma unroll
        for (int j = 0; j < 8; j++)
#pragma unroll
            for (int r = 0; r < 4; r++) acc[i][j][r] = 0.0f;

    /* 128 threads: A = 1024 16B-chunks (8/thread), B = 1024 (8/thread) */
    auto load_tiles = [&](int kt, int stg) {
        const int kb = kt * BK;
        const __half* asrc = (kb < D_) ? h_X : h_AV;
        const int akb = (kb < D_) ? kb : (kb - D_);
        __half* As = Asm + stg * (BM * PITCH);
        __half* Bs = Bsm + stg * (BN * PITCH);
#pragma unroll
        for (int j = 0; j < 8; ++j) {
            int idx = tid + 128 * j;
            int row = idx >> 3;
            int off = (idx & 7) * 8;
            cp_async16(As + row * PITCH + off,
                       asrc + (size_t)(row0 + row) * D_ + akb + off);
        }
#pragma unroll
        for (int j = 0; j < 8; ++j) {
            int idx = tid + 128 * j;
            int n   = idx >> 3;
            int off = (idx & 7) * 8;
            int o = (n < 64) ? (d0 + n) : (D_ + d0 + (n - 64));
            cp_async16(Bs + n * PITCH + off,
                       h_W + (size_t)o * K_ + kb + off);
        }
        cp_commit();
    };

    load_tiles(0, 0);
    load_tiles(1, 1);

    for (int kt = 0; kt < KTILES; ++kt) {
        if (kt + 2 < KTILES) cp_wait<1>();
        else                 cp_wait<0>();
        __syncthreads();

        if (kt + 2 < KTILES) load_tiles(kt + 2, (kt + 2) % STAGES);

        const int st = kt % STAGES;
        const uint32_t a_base = As_u32 + 2 * (st * (BM * PITCH) + warp_m * 64 * PITCH + a_lane);
        const uint32_t b_base = Bs_u32 + 2 * (st * (BN * PITCH) + b_lane);

#pragma unroll
        for (int ks = 0; ks < 4; ++ks) {
            uint32_t aR[4][4];
            uint32_t bR[8][2];
#pragma unroll
            for (int mt = 0; mt < 4; ++mt)
                ldsm_x4(aR[mt][0], aR[mt][1], aR[mt][2], aR[mt][3],
                        a_base + 2 * (mt * 16 * PITCH + ks * 16));
#pragma unroll
            for (int ntp = 0; ntp < 4; ++ntp) {
                int nt = 2 * ntp;
                int fnt = (nt < 4) ? (warp_n * 32 + nt * 8)
                                   : (64 + warp_n * 32 + (nt - 4) * 8);
                ldsm_x4(bR[nt][0], bR[nt][1], bR[nt + 1][0], bR[nt + 1][1],
                        b_base + 2 * (fnt * PITCH + ks * 16));
            }
#pragma unroll
            for (int mt = 0; mt < 4; ++mt)
#pragma unroll
                for (int nt = 0; nt < 8; ++nt)
                    mma_f16(acc[mt][nt], aR[mt], bR[nt]);
        }
    }

    /* ---- fused epilogue: thread holds contiguous d pair (2lc, 2lc+1) ---- */
#pragma unroll
    for (int mt = 0; mt < 4; ++mt) {
#pragma unroll
        for (int nt = 0; nt < 4; ++nt) {
            int d = d0 + warp_n * 32 + nt * 8 + 2 * lc;
            float2 bin = *reinterpret_cast<const float2*>(bias + d);
            float2 bfg = *reinterpret_cast<const float2*>(bias + D_ + d);

            int row = row0 + warp_m * 64 + mt * 16 + lr;
            {
                size_t off = (size_t)row * D_ + d;
                float2 xv = *reinterpret_cast<const float2*>(X + off);
                float2 av = *reinterpret_cast<const float2*>(AV + off);
                float2 o;
                o.x = sigmoidf_(acc[mt][nt][0] + bin.x) * xv.x +
                      sigmoidf_(acc[mt][nt + 4][0] + bfg.x) * av.x;
                o.y = sigmoidf_(acc[mt][nt][1] + bin.y) * xv.y +
                      sigmoidf_(acc[mt][nt + 4][1] + bfg.y) * av.y;
                *reinterpret_cast<float2*>(out + off) = o;
            }
            {
                size_t off = (size_t)(row + 8) * D_ + d;
                float2 xv = *reinterpret_cast<const float2*>(X + off);
                float2 av = *reinterpret_cast<const float2*>(AV + off);
                float2 o;
                o.x = sigmoidf_(acc[mt][nt][2] + bin.x) * xv.x +
                      sigmoidf_(acc[mt][nt + 4][2] + bfg.x) * av.x;
                o.y = sigmoidf_(acc[mt][nt][3] + bin.y) * xv.y +
                      sigmoidf_(acc[mt][nt + 4][3] + bfg.y) * av.y;
                *reinterpret_cast<float2*>(out + off) = o;
            }
        }
    }
}

/* ======================= host ======================= */
extern "C" void kernel_launch(void* const* d_in, const int* in_sizes, int n_in,
                              void* d_out, int out_size) {
    (void)in_sizes; (void)n_in; (void)out_size;
    const float* X    = (const float*)d_in[0];
    const float* W    = (const float*)d_in[1];
    const float* bias = (const float*)d_in[2];

    float* gating = (float*)d_out;
    float* avg    = (float*)d_out + (size_t)NTOT * D_;

    static bool attr_set = false;
    if (!attr_set) {
        cudaFuncSetAttribute(gate_gemm_f16,
                             cudaFuncAttributeMaxDynamicSharedMemorySize, SMEM_BYTES);
        attr_set = true;
    }

    cumavg_part_cvt<<<PART_BLOCKS + CVT_BLOCKS, 256>>>(X, W);
    chunk_prefix<<<B_, 256>>>();
    cumavg_scan_v3<<<PART_BLOCKS, 256>>>(X, avg);

    dim3 grid(D_ / 64, NTOT / BM);   /* (16, 128) */
    gate_gemm_f16<<<grid, 128, SMEM_BYTES>>>(X, avg, bias, gating);
}